// round 2
// baseline (speedup 1.0000x reference)
#include <cuda_runtime.h>
#include <cuda_bf16.h>

// ---------------------------------------------------------------------------
// BiGRIL collapsed forward.
//
// Key fact: h == 0 everywhere, so the whole network up to the PReLU is affine
// in (x1, mask, s1, s2, colsum[n]) where
//   x1  = mask ? x : b_fs[0]
//   s1[b,m,t] = sum_n adj[n,m] * x1[b,n,t]
//   s2[b,m,t] = sum_n adj[n,m] * mask[b,n,t]
//   cs[m]     = sum_n adj[n,m]
// o_pre[o] = C0[o]*x1 + C1[o]*m + C2[o]*s1 + C3[o]*s2 + C4[o]*cs + C5[o]
// out      = MLP( W_ro . prelu(o_pre) + b_ro )
// ---------------------------------------------------------------------------

#define Bdim 8
#define Cdim 1
#define Ndim 1024
#define Tdim 64
#define Hdim 64
#define NCOLS 512            // B*T
#define TOTAL (Bdim*Ndim*Tdim)

// scratch (static device memory; no allocations)
__device__ float g_S[Ndim * 1024];   // [m][j], j<512: s1, j>=512: s2  (4 MB)
__device__ float g_cs[Ndim];
__device__ float g_C[6 * Hdim];

// ---------------------------------------------------------------------------
// Kernel 1: fold weights into coefficient vectors C0..C5; zero g_cs.
// one block, 64 threads.
// ---------------------------------------------------------------------------
__global__ void coeff_kernel(const float* __restrict__ W_in,
                             const float* __restrict__ b_in,
                             const float* __restrict__ W_gc,
                             const float* __restrict__ b_gc,
                             const float* __restrict__ W_lo,
                             const float* __restrict__ b_lo) {
    __shared__ float w0[64], w1[64], bi[64];
    __shared__ float A[6][64];
    int t = threadIdx.x;   // 64 threads
    if (t < 64) {
        w0[t] = W_in[t * 66 + 0];
        w1[t] = W_in[t * 66 + 1];
        bi[t] = b_in[t];
    }
    __syncthreads();
    if (t < 64) {
        float a0 = 0.f, a1 = 0.f, a2 = 0.f, a3 = 0.f, a4 = 0.f, a5 = 0.f;
        #pragma unroll 8
        for (int k = 0; k < 64; k++) {
            float g1 = W_gc[t * 128 + k];
            float g2 = W_gc[t * 128 + 64 + k];
            a0 = fmaf(g1, w0[k], a0);
            a1 = fmaf(g1, w1[k], a1);
            a5 = fmaf(g1, bi[k], a5);
            a2 = fmaf(g2, w0[k], a2);
            a3 = fmaf(g2, w1[k], a3);
            a4 = fmaf(g2, bi[k], a4);
        }
        A[0][t] = a0; A[1][t] = a1; A[2][t] = a2;
        A[3][t] = a3; A[4][t] = a4; A[5][t] = a5 + b_gc[t];
    }
    __syncthreads();
    if (t < 64) {
        float c0 = 0.f, c1 = 0.f, c2 = 0.f, c3 = 0.f, c4 = 0.f, c5 = 0.f;
        #pragma unroll 8
        for (int k = 0; k < 64; k++) {
            float wl = W_lo[t * 128 + k];   // first 64 cols only (rest hit h=0)
            c0 = fmaf(wl, A[0][k], c0);
            c1 = fmaf(wl, A[1][k], c1);
            c2 = fmaf(wl, A[2][k], c2);
            c3 = fmaf(wl, A[3][k], c3);
            c4 = fmaf(wl, A[4][k], c4);
            c5 = fmaf(wl, A[5][k], c5);
        }
        c5 += b_lo[t];
        g_C[0 * 64 + t] = c0; g_C[1 * 64 + t] = c1; g_C[2 * 64 + t] = c2;
        g_C[3 * 64 + t] = c3; g_C[4 * 64 + t] = c4; g_C[5 * 64 + t] = c5;
    }
    // zero colsum accumulator
    for (int i = t; i < Ndim; i += 64) g_cs[i] = 0.f;
}

// ---------------------------------------------------------------------------
// Kernel 2: column sums of adj.  grid(16) x 256 threads.
// block bx: m-range = (bx&3)*256, n-chunk = bx>>2 (256 rows each).
// ---------------------------------------------------------------------------
__global__ void colsum_kernel(const float* __restrict__ adj) {
    int m = (blockIdx.x & 3) * 256 + threadIdx.x;
    int n0 = (blockIdx.x >> 2) * 256;
    float s = 0.f;
    #pragma unroll 8
    for (int n = n0; n < n0 + 256; n++)
        s += adj[n * Ndim + m];
    atomicAdd(&g_cs[m], s);
}

// ---------------------------------------------------------------------------
// Kernel 3: S = adj^T * R  where R[n, j]:
//   j <  512: x1(b = j/64, n, t = j%64)   (built on the fly)
//   j >= 512: float(mask(b = (j-512)/64, n, t))
// S stored row-major [m][j].  Tiles 64x64, BK=16, 256 threads, 4x4 microtile.
// grid: (16 j-tiles, 16 m-tiles)
// ---------------------------------------------------------------------------
__global__ void gemm_kernel(const float* __restrict__ adj,
                            const float* __restrict__ x,
                            const int*   __restrict__ mask,
                            const float* __restrict__ b_fs) {
    __shared__ float As[16][64];
    __shared__ float Bs[16][64];

    const int tid = threadIdx.x;          // 256
    const int tx = tid & 15;              // j micro group
    const int ty = tid >> 4;              // m micro group
    const int m0 = blockIdx.y * 64;
    const int j0 = blockIdx.x * 64;
    const bool maskReg = (j0 >= NCOLS);
    const int  bcol = (maskReg ? (j0 - NCOLS) : j0) >> 6;  // batch of this tile
    const float bfs0 = b_fs[0];

    const int lk  = tid >> 4;             // 0..15 : k row to load
    const int lm4 = (tid & 15) << 2;      // 0..60 : 4-wide column offset

    float acc[4][4];
    #pragma unroll
    for (int i = 0; i < 4; i++)
        #pragma unroll
        for (int j = 0; j < 4; j++) acc[i][j] = 0.f;

    for (int k0 = 0; k0 < Ndim; k0 += 16) {
        // adj tile: As[k][m]  (m contiguous -> coalesced float4)
        float4 av = *(const float4*)&adj[(k0 + lk) * Ndim + m0 + lm4];
        *(float4*)&As[lk][lm4] = av;

        // R tile
        int n = k0 + lk;
        int g = bcol * (Ndim * Tdim) + n * Tdim + lm4;  // x/mask flat index
        int4 mk = *(const int4*)&mask[g];
        float4 bv;
        if (maskReg) {
            bv.x = (float)mk.x; bv.y = (float)mk.y;
            bv.z = (float)mk.z; bv.w = (float)mk.w;
        } else {
            float4 xv = *(const float4*)&x[g];
            bv.x = mk.x ? xv.x : bfs0;
            bv.y = mk.y ? xv.y : bfs0;
            bv.z = mk.z ? xv.z : bfs0;
            bv.w = mk.w ? xv.w : bfs0;
        }
        *(float4*)&Bs[lk][lm4] = bv;

        __syncthreads();

        #pragma unroll
        for (int k = 0; k < 16; k++) {
            float4 a = *(const float4*)&As[k][ty << 2];
            float4 b = *(const float4*)&Bs[k][tx << 2];
            acc[0][0] = fmaf(a.x, b.x, acc[0][0]);
            acc[0][1] = fmaf(a.x, b.y, acc[0][1]);
            acc[0][2] = fmaf(a.x, b.z, acc[0][2]);
            acc[0][3] = fmaf(a.x, b.w, acc[0][3]);
            acc[1][0] = fmaf(a.y, b.x, acc[1][0]);
            acc[1][1] = fmaf(a.y, b.y, acc[1][1]);
            acc[1][2] = fmaf(a.y, b.z, acc[1][2]);
            acc[1][3] = fmaf(a.y, b.w, acc[1][3]);
            acc[2][0] = fmaf(a.z, b.x, acc[2][0]);
            acc[2][1] = fmaf(a.z, b.y, acc[2][1]);
            acc[2][2] = fmaf(a.z, b.z, acc[2][2]);
            acc[2][3] = fmaf(a.z, b.w, acc[2][3]);
            acc[3][0] = fmaf(a.w, b.x, acc[3][0]);
            acc[3][1] = fmaf(a.w, b.y, acc[3][1]);
            acc[3][2] = fmaf(a.w, b.z, acc[3][2]);
            acc[3][3] = fmaf(a.w, b.w, acc[3][3]);
        }
        __syncthreads();
    }

    #pragma unroll
    for (int i = 0; i < 4; i++) {
        float4 st = make_float4(acc[i][0], acc[i][1], acc[i][2], acc[i][3]);
        *(float4*)&g_S[(m0 + (ty << 2) + i) * 1024 + j0 + (tx << 2)] = st;
    }
}

// ---------------------------------------------------------------------------
// Kernel 4: per-element tail.  grid 2048 x 256.
// ---------------------------------------------------------------------------
__global__ void final_kernel(const float* __restrict__ x,
                             const int*   __restrict__ mask,
                             const float* __restrict__ b_fs,
                             const float* __restrict__ prelu_a,
                             const float* __restrict__ W_ro,
                             const float* __restrict__ b_ro,
                             const float* __restrict__ W_o1,
                             const float* __restrict__ b_o1,
                             const float* __restrict__ W_o2,
                             const float* __restrict__ b_o2,
                             float* __restrict__ out) {
    __shared__ float sC[6][64], swro[64], swo1[64], sbo1[64], swo2[64];
    int t = threadIdx.x;
    if (t < 64) {
        #pragma unroll
        for (int i = 0; i < 6; i++) sC[i][t] = g_C[i * 64 + t];
        swro[t] = W_ro[t];      // first 64 cols; cols 64..127 hit h=0
        swo1[t] = W_o1[t];
        sbo1[t] = b_o1[t];
        swo2[t] = W_o2[t];
    }
    __syncthreads();

    int idx = blockIdx.x * blockDim.x + t;
    if (idx >= TOTAL) return;

    const float bfs0 = b_fs[0];
    const float a    = prelu_a[0];

    int   mi = mask[idx];
    float mF = (float)mi;
    float xv = x[idx];
    float x1 = mi ? xv : bfs0;

    int n  = (idx >> 6) & (Ndim - 1);
    int b  = idx >> 16;          // / (Ndim*Tdim)
    int tt = idx & 63;
    int j  = (b << 6) | tt;

    float s1 = g_S[n * 1024 + j];
    float s2 = g_S[n * 1024 + NCOLS + j];
    float cs = g_cs[n];

    float xs2 = b_ro[0];
    #pragma unroll
    for (int o = 0; o < 64; o++) {
        float v = sC[5][o];
        v = fmaf(sC[0][o], x1, v);
        v = fmaf(sC[1][o], mF, v);
        v = fmaf(sC[2][o], s1, v);
        v = fmaf(sC[3][o], s2, v);
        v = fmaf(sC[4][o], cs, v);
        float p = (v >= 0.f) ? v : a * v;
        xs2 = fmaf(swro[o], p, xs2);
    }

    float acc = b_o2[0];
    #pragma unroll
    for (int f = 0; f < 64; f++) {
        float y = fmaf(swo1[f], xs2, sbo1[f]);
        y = fmaxf(y, 0.f);
        acc = fmaf(swo2[f], y, acc);
    }
    out[idx] = acc;
}

// ---------------------------------------------------------------------------
extern "C" void kernel_launch(void* const* d_in, const int* in_sizes, int n_in,
                              void* d_out, int out_size) {
    const float* x     = (const float*)d_in[0];
    const int*   mask  = (const int*)  d_in[1];
    // d_in[2] = W_fs (unused: multiplies h=0)
    const float* b_fs  = (const float*)d_in[3];
    const float* W_in  = (const float*)d_in[4];
    const float* b_in  = (const float*)d_in[5];
    const float* adj   = (const float*)d_in[6];
    const float* W_gc  = (const float*)d_in[7];
    const float* b_gc  = (const float*)d_in[8];
    const float* W_lo  = (const float*)d_in[9];
    const float* b_lo  = (const float*)d_in[10];
    const float* pre_a = (const float*)d_in[11];
    const float* W_ro  = (const float*)d_in[12];
    const float* b_ro  = (const float*)d_in[13];
    const float* W_o1  = (const float*)d_in[14];
    const float* b_o1  = (const float*)d_in[15];
    const float* W_o2  = (const float*)d_in[16];
    const float* b_o2  = (const float*)d_in[17];
    float* out = (float*)d_out;

    coeff_kernel<<<1, 64>>>(W_in, b_in, W_gc, b_gc, W_lo, b_lo);
    colsum_kernel<<<16, 256>>>(adj);
    {
        dim3 grid(16, 16);
        gemm_kernel<<<grid, 256>>>(adj, x, mask, b_fs);
    }
    final_kernel<<<TOTAL / 256, 256>>>(x, mask, b_fs, pre_a, W_ro, b_ro,
                                       W_o1, b_o1, W_o2, b_o2, out);
}

// round 5
// speedup vs baseline: 1.5785x; 1.5785x over previous
#include <cuda_runtime.h>
#include <cuda_bf16.h>
#include <cstdint>

#define Bdim 8
#define Ndim 1024
#define Tdim 64
#define TOTAL (Bdim*Ndim*Tdim)

__device__ float g_S[Ndim * 1024];   // [m][j], j<512: s1, j>=512: s2
__device__ float g_cs[Ndim];
__device__ float g_C[6 * 64];
__device__ float g_beta[64];
__device__ float g_gamma[6];
__device__ float g_knots[127];
__device__ float g_slope[65];
__device__ float g_inter[65];

// ------------------------------ helpers -----------------------------------
__device__ __forceinline__ uint32_t smem_u32(const void* p) {
    uint32_t a;
    asm("{ .reg .u64 t; cvta.to.shared.u64 t, %1; cvt.u32.u64 %0, t; }"
        : "=r"(a) : "l"(p));
    return a;
}
__device__ __forceinline__ uint32_t pack_bf16x2(float lo, float hi) {
    uint32_t r;
    asm("cvt.rn.bf16x2.f32 %0, %1, %2;" : "=r"(r) : "f"(hi), "f"(lo));
    return r;
}
__device__ __forceinline__ void ldsm_x4_t(uint32_t& r0, uint32_t& r1,
                                          uint32_t& r2, uint32_t& r3,
                                          uint32_t addr) {
    asm volatile("ldmatrix.sync.aligned.m8n8.x4.trans.shared.b16 "
                 "{%0,%1,%2,%3}, [%4];"
                 : "=r"(r0), "=r"(r1), "=r"(r2), "=r"(r3) : "r"(addr));
}
__device__ __forceinline__ void mma16816(float* c, const uint32_t* a,
                                         const uint32_t* b) {
    asm volatile(
        "mma.sync.aligned.m16n8k16.row.col.f32.bf16.bf16.f32 "
        "{%0,%1,%2,%3}, {%4,%5,%6,%7}, {%8,%9}, {%0,%1,%2,%3};"
        : "+f"(c[0]), "+f"(c[1]), "+f"(c[2]), "+f"(c[3])
        : "r"(a[0]), "r"(a[1]), "r"(a[2]), "r"(a[3]), "r"(b[0]), "r"(b[1]));
}

// ---------------------------------------------------------------------------
// Kernel 1: coefficient folding + piecewise-linear MLP tables. 1 block x 128.
// ---------------------------------------------------------------------------
__global__ void coeff_kernel(const float* __restrict__ W_in,
                             const float* __restrict__ b_in,
                             const float* __restrict__ W_gc,
                             const float* __restrict__ b_gc,
                             const float* __restrict__ W_lo,
                             const float* __restrict__ b_lo,
                             const float* __restrict__ prelu_a,
                             const float* __restrict__ W_ro,
                             const float* __restrict__ b_ro,
                             const float* __restrict__ W_o1,
                             const float* __restrict__ b_o1,
                             const float* __restrict__ W_o2,
                             const float* __restrict__ b_o2) {
    __shared__ float w0[64], w1[64], bi[64];
    __shared__ float A[6][64];
    __shared__ float sC[6][64];
    __shared__ float sAl[64];
    __shared__ float kno[64], srt[64];
    __shared__ int   srank[64];
    __shared__ float sw1[64], sb1[64], sw2[64];
    int t = threadIdx.x;

    if (t < 64) {
        w0[t] = W_in[t * 66 + 0];
        w1[t] = W_in[t * 66 + 1];
        bi[t] = b_in[t];
    }
    __syncthreads();
    if (t < 64) {
        float a0 = 0.f, a1 = 0.f, a2 = 0.f, a3 = 0.f, a4 = 0.f, a5 = 0.f;
        for (int k = 0; k < 64; k++) {
            float g1 = W_gc[t * 128 + k];
            float g2 = W_gc[t * 128 + 64 + k];
            a0 = fmaf(g1, w0[k], a0); a1 = fmaf(g1, w1[k], a1);
            a5 = fmaf(g1, bi[k], a5);
            a2 = fmaf(g2, w0[k], a2); a3 = fmaf(g2, w1[k], a3);
            a4 = fmaf(g2, bi[k], a4);
        }
        A[0][t] = a0; A[1][t] = a1; A[2][t] = a2;
        A[3][t] = a3; A[4][t] = a4; A[5][t] = a5 + b_gc[t];
    }
    __syncthreads();
    if (t < 64) {
        float c[6] = {0.f, 0.f, 0.f, 0.f, 0.f, 0.f};
        for (int k = 0; k < 64; k++) {
            float wl = W_lo[t * 128 + k];
            #pragma unroll
            for (int i = 0; i < 6; i++) c[i] = fmaf(wl, A[i][k], c[i]);
        }
        c[5] += b_lo[t];
        #pragma unroll
        for (int i = 0; i < 6; i++) { sC[i][t] = c[i]; g_C[i * 64 + t] = c[i]; }
        float a = prelu_a[0];
        float wr = W_ro[t];
        sAl[t] = wr * 0.5f * (1.f + a);
        g_beta[t] = wr * 0.5f * (1.f - a);
        sw1[t] = W_o1[t]; sb1[t] = b_o1[t]; sw2[t] = W_o2[t];
    }
    __syncthreads();
    if (t < 6) {
        float g = 0.f;
        for (int k = 0; k < 64; k++) g = fmaf(sAl[k], sC[t][k], g);
        if (t == 5) g += b_ro[0];
        g_gamma[t] = g;
    }
    if (t < 64) {
        float w = sw1[t];
        kno[t] = (w != 0.f) ? (-sb1[t] / w) : 3.0e38f;
    }
    __syncthreads();
    if (t < 64) {
        float kt = kno[t];
        int r = 0;
        for (int j = 0; j < 64; j++)
            r += (kno[j] < kt) || (kno[j] == kt && j < t);
        srank[t] = r;
        srt[r] = kt;
    }
    __syncthreads();
    if (t < 64) g_knots[t] = srt[t];
    for (int i = 64 + t; i < 127; i += blockDim.x) g_knots[i] = 3.2e38f;
    if (t < 65) {
        float sl = 0.f, in = b_o2[0];
        for (int f = 0; f < 64; f++) {
            float w = sw1[f], w2 = sw2[f];
            if (w > 0.f) {
                if (srank[f] < t) { sl = fmaf(w2, w, sl); in = fmaf(w2, sb1[f], in); }
            } else if (w < 0.f) {
                if (srank[f] >= t) { sl = fmaf(w2, w, sl); in = fmaf(w2, sb1[f], in); }
            } else {
                in = fmaf(w2, fmaxf(sb1[f], 0.f), in);
            }
        }
        g_slope[t] = sl; g_inter[t] = in;
    }
    for (int i = t; i < Ndim; i += blockDim.x) g_cs[i] = 0.f;
}

// ---------------------------------------------------------------------------
// Kernel 2: column sums of adj. 32 blocks x 256.
// ---------------------------------------------------------------------------
__global__ void colsum_kernel(const float* __restrict__ adj) {
    int m = (blockIdx.x & 3) * 256 + threadIdx.x;
    int n0 = (blockIdx.x >> 2) * 128;
    float s = 0.f;
    #pragma unroll 8
    for (int n = n0; n < n0 + 128; n++)
        s += adj[n * Ndim + m];
    atomicAdd(&g_cs[m], s);
}

// ---------------------------------------------------------------------------
// Kernel 3: bf16 split-GEMM on tensor cores via mma.sync (sm_100-safe).
//   S = adj^T * R, fp32 accumulate, splits hi*hi + hi*lo + lo*hi.
//   CTA: D[128 m, 64 j]; K=1024 in 64-chunks, double-buffered smem.
//   grid (16 j-tiles, 8 m-tiles), 256 threads = 8 warps (4 m x 2 j).
// ---------------------------------------------------------------------------
#define KC 64
#define A_STRIDE_B 272      // 136 bf16 per row
#define B_STRIDE_B 144      // 72 bf16 per row
#define A_STAGE (KC * A_STRIDE_B)   // 17408
#define B_STAGE (KC * B_STRIDE_B)   // 9216
#define OFF_AHI 0
#define OFF_ALO (2 * A_STAGE)               // 34816
#define OFF_BHI (4 * A_STAGE)               // 69632
#define OFF_BLO (4 * A_STAGE + 2 * B_STAGE) // 88064
#define GEMM_SMEM (4 * A_STAGE + 4 * B_STAGE)  // 106496

__global__ void __launch_bounds__(256)
gemm_mma_kernel(const float* __restrict__ adj,
                const float* __restrict__ x,
                const int*   __restrict__ mask,
                const float* __restrict__ b_fs) {
    extern __shared__ __align__(16) char smp[];
    const uint32_t sb = smem_u32(smp);

    const int tid  = threadIdx.x;
    const int lane = tid & 31;
    const int wid  = tid >> 5;
    const int warp_m = (wid & 3) * 32;
    const int warp_j = (wid >> 2) * 32;
    const int mcta = blockIdx.y * 128;
    const int bx   = blockIdx.x;
    const bool isMask = (bx >= 8);
    const int bcol = isMask ? bx - 8 : bx;
    const float bfs0 = b_fs[0];

    // ldmatrix per-lane address components
    const int aK = (lane & 7) + ((lane & 16) ? 8 : 0);
    const int aM = (lane & 8) ? 8 : 0;
    const int bK = (lane & 7) + ((lane & 8) ? 8 : 0);
    const int bJ = (lane & 16) ? 8 : 0;
    const uint32_t aBase = sb + OFF_AHI + (uint32_t)(aK * A_STRIDE_B + (warp_m + aM) * 2);
    const uint32_t bBase = sb + OFF_BHI + (uint32_t)(bK * B_STRIDE_B + (warp_j + bJ) * 2);

    // staging registers
    uint2 sAh[8], sAl[8], sBh[4], sBl[4];
    const int aRow = tid >> 5;          // + 8*p
    const int aCol = lane * 4;          // m within tile
    const int bRow = tid >> 2;          // k
    const int bC0  = (tid & 3) * 4;     // + 16*q floats

    float acc[2][4][4];
    #pragma unroll
    for (int mt = 0; mt < 2; mt++)
        #pragma unroll
        for (int nt = 0; nt < 4; nt++)
            #pragma unroll
            for (int r = 0; r < 4; r++) acc[mt][nt][r] = 0.f;

    auto load_chunk = [&](int it) {
        const int k0 = it * KC;
        #pragma unroll
        for (int p = 0; p < 8; p++) {
            int k = aRow + p * 8;
            float4 a = *(const float4*)&adj[(k0 + k) * Ndim + mcta + aCol];
            uint32_t ux = __float_as_uint(a.x), uy = __float_as_uint(a.y);
            uint32_t uz = __float_as_uint(a.z), uw = __float_as_uint(a.w);
            sAh[p].x = __byte_perm(ux, uy, 0x7632);
            sAh[p].y = __byte_perm(uz, uw, 0x7632);
            sAl[p].x = pack_bf16x2(a.x - __uint_as_float(ux & 0xFFFF0000u),
                                   a.y - __uint_as_float(uy & 0xFFFF0000u));
            sAl[p].y = pack_bf16x2(a.z - __uint_as_float(uz & 0xFFFF0000u),
                                   a.w - __uint_as_float(uw & 0xFFFF0000u));
        }
        #pragma unroll
        for (int q = 0; q < 4; q++) {
            int g = bcol * 65536 + (k0 + bRow) * Tdim + bC0 + q * 16;
            int4 mk = *(const int4*)&mask[g];
            float4 v;
            if (isMask) {
                v = make_float4((float)mk.x, (float)mk.y, (float)mk.z, (float)mk.w);
            } else {
                float4 xv = *(const float4*)&x[g];
                v.x = mk.x ? xv.x : bfs0;
                v.y = mk.y ? xv.y : bfs0;
                v.z = mk.z ? xv.z : bfs0;
                v.w = mk.w ? xv.w : bfs0;
            }
            uint32_t ux = __float_as_uint(v.x), uy = __float_as_uint(v.y);
            uint32_t uz = __float_as_uint(v.z), uw = __float_as_uint(v.w);
            sBh[q].x = __byte_perm(ux, uy, 0x7632);
            sBh[q].y = __byte_perm(uz, uw, 0x7632);
            sBl[q].x = pack_bf16x2(v.x - __uint_as_float(ux & 0xFFFF0000u),
                                   v.y - __uint_as_float(uy & 0xFFFF0000u));
            sBl[q].y = pack_bf16x2(v.z - __uint_as_float(uz & 0xFFFF0000u),
                                   v.w - __uint_as_float(uw & 0xFFFF0000u));
        }
    };

    auto sts_chunk = [&](int s) {
        #pragma unroll
        for (int p = 0; p < 8; p++) {
            int k = aRow + p * 8;
            int off = s * A_STAGE + k * A_STRIDE_B + lane * 8;
            *(uint2*)(smp + OFF_AHI + off) = sAh[p];
            *(uint2*)(smp + OFF_ALO + off) = sAl[p];
        }
        #pragma unroll
        for (int q = 0; q < 4; q++) {
            int off = s * B_STAGE + bRow * B_STRIDE_B + (bC0 + q * 16) * 2;
            *(uint2*)(smp + OFF_BHI + off) = sBh[q];
            *(uint2*)(smp + OFF_BLO + off) = sBl[q];
        }
    };

    auto compute = [&](int s) {
        const uint32_t aS = aBase + s * A_STAGE;
        const uint32_t bS = bBase + s * B_STAGE;
        #pragma unroll
        for (int ks = 0; ks < 4; ks++) {
            uint32_t aKaddr = aS + ks * (16 * A_STRIDE_B);
            uint32_t bKaddr = bS + ks * (16 * B_STRIDE_B);
            uint32_t ah[2][4], al[2][4], bh[2][4], bl[2][4];
            ldsm_x4_t(ah[0][0], ah[0][1], ah[0][2], ah[0][3], aKaddr);
            ldsm_x4_t(ah[1][0], ah[1][1], ah[1][2], ah[1][3], aKaddr + 32);
            ldsm_x4_t(al[0][0], al[0][1], al[0][2], al[0][3], aKaddr + (OFF_ALO - OFF_AHI));
            ldsm_x4_t(al[1][0], al[1][1], al[1][2], al[1][3], aKaddr + (OFF_ALO - OFF_AHI) + 32);
            ldsm_x4_t(bh[0][0], bh[0][1], bh[0][2], bh[0][3], bKaddr);
            ldsm_x4_t(bh[1][0], bh[1][1], bh[1][2], bh[1][3], bKaddr + 32);
            ldsm_x4_t(bl[0][0], bl[0][1], bl[0][2], bl[0][3], bKaddr + (OFF_BLO - OFF_BHI));
            ldsm_x4_t(bl[1][0], bl[1][1], bl[1][2], bl[1][3], bKaddr + (OFF_BLO - OFF_BHI) + 32);
            #pragma unroll
            for (int mt = 0; mt < 2; mt++)
                #pragma unroll
                for (int nt = 0; nt < 4; nt++) {
                    const uint32_t* Bh = &bh[nt >> 1][(nt & 1) * 2];
                    const uint32_t* Bl = &bl[nt >> 1][(nt & 1) * 2];
                    mma16816(acc[mt][nt], ah[mt], Bh);
                    mma16816(acc[mt][nt], ah[mt], Bl);
                    mma16816(acc[mt][nt], al[mt], Bh);
                }
        }
    };

    load_chunk(0);
    sts_chunk(0);
    __syncthreads();
    for (int it = 0; it < 16; ++it) {
        if (it < 15) load_chunk(it + 1);
        compute(it & 1);
        if (it < 15) {
            sts_chunk((it + 1) & 1);
            __syncthreads();
        }
    }

    // epilogue: acc -> g_S
    const int gid = lane >> 2, tig = lane & 3;
    const int j0 = bx * 64 + warp_j + 2 * tig;
    #pragma unroll
    for (int mt = 0; mt < 2; mt++) {
        int m = mcta + warp_m + mt * 16 + gid;
        #pragma unroll
        for (int nt = 0; nt < 4; nt++) {
            int j = j0 + nt * 8;
            *(float2*)&g_S[m * 1024 + j] =
                make_float2(acc[mt][nt][0], acc[mt][nt][1]);
            *(float2*)&g_S[(m + 8) * 1024 + j] =
                make_float2(acc[mt][nt][2], acc[mt][nt][3]);
        }
    }
}

// ---------------------------------------------------------------------------
// Kernel 4: per-element tail, E=4 elements/thread. 512 blocks x 256.
// ---------------------------------------------------------------------------
__global__ void __launch_bounds__(256)
final_kernel(const float* __restrict__ x,
             const int*   __restrict__ mask,
             const float* __restrict__ b_fs,
             float* __restrict__ out) {
    __shared__ float sc0[64], sc1[64], sc2[64], sc3[64], sc4[64], sc5[64], sbt[64];
    __shared__ float skn[127], ssl[65], sit[65], sg[6];
    int t = threadIdx.x;
    if (t < 64) {
        sc0[t] = g_C[t];         sc1[t] = g_C[64 + t];
        sc2[t] = g_C[128 + t];   sc3[t] = g_C[192 + t];
        sc4[t] = g_C[256 + t];   sc5[t] = g_C[320 + t];
        sbt[t] = g_beta[t];
    }
    if (t < 127) skn[t] = g_knots[t];
    if (t < 65) { ssl[t] = g_slope[t]; sit[t] = g_inter[t]; }
    if (t < 6) sg[t] = g_gamma[t];
    __syncthreads();

    const float bfs0 = b_fs[0];
    const int base = blockIdx.x * 1024 + t;

    float x1[4], mf[4], s1[4], s2[4], csv[4], acc[4];
    #pragma unroll
    for (int e = 0; e < 4; e++) {
        int idx = base + e * 256;
        int mi = mask[idx];
        float xv = x[idx];
        mf[e] = (float)mi;
        x1[e] = mi ? xv : bfs0;
        int n = (idx >> 6) & (Ndim - 1);
        int b = idx >> 16;
        int tt = idx & 63;
        int j = (b << 6) | tt;
        s1[e] = g_S[n * 1024 + j];
        s2[e] = g_S[n * 1024 + 512 + j];
        csv[e] = g_cs[n];
        acc[e] = 0.f;
    }

    #pragma unroll
    for (int o = 0; o < 64; o++) {
        float k0 = sc0[o], k1 = sc1[o], k2 = sc2[o], k3 = sc3[o];
        float k4 = sc4[o], k5 = sc5[o], bt = sbt[o];
        #pragma unroll
        for (int e = 0; e < 4; e++) {
            float v = fmaf(k4, csv[e], k5);
            v = fmaf(k1, mf[e], v);
            v = fmaf(k3, s2[e], v);
            v = fmaf(k2, s1[e], v);
            v = fmaf(k0, x1[e], v);
            acc[e] = fmaf(bt, fabsf(v), acc[e]);
        }
    }

    #pragma unroll
    for (int e = 0; e < 4; e++) {
        float xs = sg[5];
        xs = fmaf(sg[0], x1[e], xs);
        xs = fmaf(sg[1], mf[e], xs);
        xs = fmaf(sg[2], s1[e], xs);
        xs = fmaf(sg[3], s2[e], xs);
        xs = fmaf(sg[4], csv[e], xs);
        xs += acc[e];
        int k = 0;
        if (skn[63] < xs) k = 64;
        if (skn[k + 31] < xs) k += 32;
        if (skn[k + 15] < xs) k += 16;
        if (skn[k + 7] < xs) k += 8;
        if (skn[k + 3] < xs) k += 4;
        if (skn[k + 1] < xs) k += 2;
        if (skn[k] < xs) k += 1;
        out[base + e * 256] = fmaf(ssl[k], xs, sit[k]);
    }
}

// ---------------------------------------------------------------------------
extern "C" void kernel_launch(void* const* d_in, const int* in_sizes, int n_in,
                              void* d_out, int out_size) {
    const float* x     = (const float*)d_in[0];
    const int*   mask  = (const int*)  d_in[1];
    const float* b_fs  = (const float*)d_in[3];
    const float* W_in  = (const float*)d_in[4];
    const float* b_in  = (const float*)d_in[5];
    const float* adj   = (const float*)d_in[6];
    const float* W_gc  = (const float*)d_in[7];
    const float* b_gc  = (const float*)d_in[8];
    const float* W_lo  = (const float*)d_in[9];
    const float* b_lo  = (const float*)d_in[10];
    const float* pre_a = (const float*)d_in[11];
    const float* W_ro  = (const float*)d_in[12];
    const float* b_ro  = (const float*)d_in[13];
    const float* W_o1  = (const float*)d_in[14];
    const float* b_o1  = (const float*)d_in[15];
    const float* W_o2  = (const float*)d_in[16];
    const float* b_o2  = (const float*)d_in[17];
    float* out = (float*)d_out;

    cudaFuncSetAttribute(gemm_mma_kernel,
                         cudaFuncAttributeMaxDynamicSharedMemorySize,
                         GEMM_SMEM);

    coeff_kernel<<<1, 128>>>(W_in, b_in, W_gc, b_gc, W_lo, b_lo,
                             pre_a, W_ro, b_ro, W_o1, b_o1, W_o2, b_o2);
    colsum_kernel<<<32, 256>>>(adj);
    {
        dim3 grid(16, 8);
        gemm_mma_kernel<<<grid, 256, GEMM_SMEM>>>(adj, x, mask, b_fs);
    }
    final_kernel<<<512, 256>>>(x, mask, b_fs, out);
}

// round 6
// speedup vs baseline: 1.8705x; 1.1850x over previous
#include <cuda_runtime.h>
#include <cuda_bf16.h>
#include <cstdint>

#define Bdim 8
#define Ndim 1024
#define Tdim 64
#define TOTAL (Bdim*Ndim*Tdim)

typedef unsigned long long u64t;

// scratch (static device memory)
__device__ float g_S[Ndim * 1024];   // [m][j], j<512: s1, j>=512: s2
__device__ float g_cs[Ndim];
__device__ float g_C[6 * 64];
__device__ float g_beta[64];
__device__ float g_gamma[6];
__device__ float g_knots[127];
__device__ float g_slope[65];
__device__ float g_inter[65];
// pre-split bf16 operands: [k][col] row-major, 1024 cols (pairs packed in u32)
__device__ __align__(16) uint32_t g_Ahi[1024 * 512];
__device__ __align__(16) uint32_t g_Alo[1024 * 512];
__device__ __align__(16) uint32_t g_Bhi[1024 * 512];
__device__ __align__(16) uint32_t g_Blo[1024 * 512];

// ------------------------------ helpers -----------------------------------
__device__ __forceinline__ uint32_t smem_u32(const void* p) {
    uint32_t a;
    asm("{ .reg .u64 t; cvta.to.shared.u64 t, %1; cvt.u32.u64 %0, t; }"
        : "=r"(a) : "l"(p));
    return a;
}
__device__ __forceinline__ uint32_t pack_bf16x2(float lo, float hi) {
    uint32_t r;
    asm("cvt.rn.bf16x2.f32 %0, %1, %2;" : "=r"(r) : "f"(hi), "f"(lo));
    return r;
}
__device__ __forceinline__ void ldsm_x4_t(uint32_t& r0, uint32_t& r1,
                                          uint32_t& r2, uint32_t& r3,
                                          uint32_t addr) {
    asm volatile("ldmatrix.sync.aligned.m8n8.x4.trans.shared.b16 "
                 "{%0,%1,%2,%3}, [%4];"
                 : "=r"(r0), "=r"(r1), "=r"(r2), "=r"(r3) : "r"(addr));
}
__device__ __forceinline__ void mma16816(float* c, const uint32_t* a,
                                         const uint32_t* b) {
    asm volatile(
        "mma.sync.aligned.m16n8k16.row.col.f32.bf16.bf16.f32 "
        "{%0,%1,%2,%3}, {%4,%5,%6,%7}, {%8,%9}, {%0,%1,%2,%3};"
        : "+f"(c[0]), "+f"(c[1]), "+f"(c[2]), "+f"(c[3])
        : "r"(a[0]), "r"(a[1]), "r"(a[2]), "r"(a[3]), "r"(b[0]), "r"(b[1]));
}
__device__ __forceinline__ void cp16(uint32_t dst, const void* src) {
    asm volatile("cp.async.cg.shared.global [%0], [%1], 16;"
                 :: "r"(dst), "l"(src) : "memory");
}
// packed f32x2 ops (Blackwell base ISA)
__device__ __forceinline__ u64t fma2(u64t a, u64t b, u64t c) {
    u64t d;
    asm("fma.rn.f32x2 %0, %1, %2, %3;" : "=l"(d) : "l"(a), "l"(b), "l"(c));
    return d;
}
__device__ __forceinline__ u64t add2(u64t a, u64t b) {
    u64t d;
    asm("add.rn.f32x2 %0, %1, %2;" : "=l"(d) : "l"(a), "l"(b));
    return d;
}
__device__ __forceinline__ u64t abs2(u64t a) {
    u64t d;
    asm("and.b64 %0, %1, 0x7FFFFFFF7FFFFFFF;" : "=l"(d) : "l"(a));
    return d;
}
__device__ __forceinline__ u64t pack2(float lo, float hi) {
    u64t d;
    asm("mov.b64 %0, {%1, %2};" : "=l"(d) : "f"(lo), "f"(hi));
    return d;
}
__device__ __forceinline__ void unpack2(float& lo, float& hi, u64t v) {
    asm("mov.b64 {%0, %1}, %2;" : "=f"(lo), "=f"(hi) : "l"(v));
}

// ---------------------------------------------------------------------------
// Kernel 0: split adj and R=(x1|mask) into bf16 hi/lo. grid 1024 x 256.
// ---------------------------------------------------------------------------
__global__ void prep_kernel(const float* __restrict__ adj,
                            const float* __restrict__ x,
                            const int*   __restrict__ mask,
                            const float* __restrict__ b_fs) {
    const int k = blockIdx.x;
    const int t = threadIdx.x;
    const float bfs0 = b_fs[0];

    // adj row: 1024 floats, thread handles 4 (one float4)
    float4 a = *(const float4*)(adj + k * 1024 + t * 4);
    uint32_t ux = __float_as_uint(a.x), uy = __float_as_uint(a.y);
    uint32_t uz = __float_as_uint(a.z), uw = __float_as_uint(a.w);
    uint2 hi, lo;
    hi.x = __byte_perm(ux, uy, 0x7632);
    hi.y = __byte_perm(uz, uw, 0x7632);
    lo.x = pack_bf16x2(a.x - __uint_as_float(ux & 0xFFFF0000u),
                       a.y - __uint_as_float(uy & 0xFFFF0000u));
    lo.y = pack_bf16x2(a.z - __uint_as_float(uz & 0xFFFF0000u),
                       a.w - __uint_as_float(uw & 0xFFFF0000u));
    *(uint2*)&g_Ahi[k * 512 + t * 2] = hi;
    *(uint2*)&g_Alo[k * 512 + t * 2] = lo;

    // R row: cols j = 2t, 2t+1 (x1 part) and 512+2t (mask part)
    int j = 2 * t;
    int b = j >> 6, tt = j & 63;
    int gi = b * 65536 + k * 64 + tt;
    int m0 = mask[gi], m1 = mask[gi + 1];
    float v0 = m0 ? x[gi] : bfs0;
    float v1 = m1 ? x[gi + 1] : bfs0;
    uint32_t u0 = __float_as_uint(v0), u1 = __float_as_uint(v1);
    g_Bhi[k * 512 + t] = __byte_perm(u0, u1, 0x7632);
    g_Blo[k * 512 + t] = pack_bf16x2(v0 - __uint_as_float(u0 & 0xFFFF0000u),
                                     v1 - __uint_as_float(u1 & 0xFFFF0000u));
    // mask cols: values 0/1 exact in bf16, lo = 0
    g_Bhi[k * 512 + 256 + t] = pack_bf16x2((float)m0, (float)m1);
    g_Blo[k * 512 + 256 + t] = 0u;
}

// ---------------------------------------------------------------------------
// Kernel 1: coefficient folding + piecewise-linear MLP tables. 1 block x 128.
// ---------------------------------------------------------------------------
__global__ void coeff_kernel(const float* __restrict__ W_in,
                             const float* __restrict__ b_in,
                             const float* __restrict__ W_gc,
                             const float* __restrict__ b_gc,
                             const float* __restrict__ W_lo,
                             const float* __restrict__ b_lo,
                             const float* __restrict__ prelu_a,
                             const float* __restrict__ W_ro,
                             const float* __restrict__ b_ro,
                             const float* __restrict__ W_o1,
                             const float* __restrict__ b_o1,
                             const float* __restrict__ W_o2,
                             const float* __restrict__ b_o2) {
    __shared__ float w0[64], w1[64], bi[64];
    __shared__ float A[6][64];
    __shared__ float sC[6][64];
    __shared__ float sAl[64];
    __shared__ float kno[64], srt[64];
    __shared__ int   srank[64];
    __shared__ float sw1[64], sb1[64], sw2[64];
    int t = threadIdx.x;

    if (t < 64) {
        w0[t] = W_in[t * 66 + 0];
        w1[t] = W_in[t * 66 + 1];
        bi[t] = b_in[t];
    }
    __syncthreads();
    if (t < 64) {
        float a0 = 0.f, a1 = 0.f, a2 = 0.f, a3 = 0.f, a4 = 0.f, a5 = 0.f;
        for (int k = 0; k < 64; k++) {
            float g1 = W_gc[t * 128 + k];
            float g2 = W_gc[t * 128 + 64 + k];
            a0 = fmaf(g1, w0[k], a0); a1 = fmaf(g1, w1[k], a1);
            a5 = fmaf(g1, bi[k], a5);
            a2 = fmaf(g2, w0[k], a2); a3 = fmaf(g2, w1[k], a3);
            a4 = fmaf(g2, bi[k], a4);
        }
        A[0][t] = a0; A[1][t] = a1; A[2][t] = a2;
        A[3][t] = a3; A[4][t] = a4; A[5][t] = a5 + b_gc[t];
    }
    __syncthreads();
    if (t < 64) {
        float c[6] = {0.f, 0.f, 0.f, 0.f, 0.f, 0.f};
        for (int k = 0; k < 64; k++) {
            float wl = W_lo[t * 128 + k];
            #pragma unroll
            for (int i = 0; i < 6; i++) c[i] = fmaf(wl, A[i][k], c[i]);
        }
        c[5] += b_lo[t];
        #pragma unroll
        for (int i = 0; i < 6; i++) { sC[i][t] = c[i]; g_C[i * 64 + t] = c[i]; }
        float a = prelu_a[0];
        float wr = W_ro[t];
        sAl[t] = wr * 0.5f * (1.f + a);
        g_beta[t] = wr * 0.5f * (1.f - a);
        sw1[t] = W_o1[t]; sb1[t] = b_o1[t]; sw2[t] = W_o2[t];
    }
    __syncthreads();
    if (t < 6) {
        float g = 0.f;
        for (int k = 0; k < 64; k++) g = fmaf(sAl[k], sC[t][k], g);
        if (t == 5) g += b_ro[0];
        g_gamma[t] = g;
    }
    if (t < 64) {
        float w = sw1[t];
        kno[t] = (w != 0.f) ? (-sb1[t] / w) : 3.0e38f;
    }
    __syncthreads();
    if (t < 64) {
        float kt = kno[t];
        int r = 0;
        for (int j = 0; j < 64; j++)
            r += (kno[j] < kt) || (kno[j] == kt && j < t);
        srank[t] = r;
        srt[r] = kt;
    }
    __syncthreads();
    if (t < 64) g_knots[t] = srt[t];
    for (int i = 64 + t; i < 127; i += blockDim.x) g_knots[i] = 3.2e38f;
    if (t < 65) {
        float sl = 0.f, in = b_o2[0];
        for (int f = 0; f < 64; f++) {
            float w = sw1[f], w2 = sw2[f];
            if (w > 0.f) {
                if (srank[f] < t) { sl = fmaf(w2, w, sl); in = fmaf(w2, sb1[f], in); }
            } else if (w < 0.f) {
                if (srank[f] >= t) { sl = fmaf(w2, w, sl); in = fmaf(w2, sb1[f], in); }
            } else {
                in = fmaf(w2, fmaxf(sb1[f], 0.f), in);
            }
        }
        g_slope[t] = sl; g_inter[t] = in;
    }
    for (int i = t; i < Ndim; i += blockDim.x) g_cs[i] = 0.f;
}

// ---------------------------------------------------------------------------
// Kernel 2: column sums of adj. 128 blocks x 256.
// ---------------------------------------------------------------------------
__global__ void colsum_kernel(const float* __restrict__ adj) {
    int m = (blockIdx.x & 3) * 256 + threadIdx.x;
    int n0 = (blockIdx.x >> 2) * 32;
    float s = 0.f;
    #pragma unroll 8
    for (int n = n0; n < n0 + 32; n++)
        s += adj[n * Ndim + m];
    atomicAdd(&g_cs[m], s);
}

// ---------------------------------------------------------------------------
// Kernel 3: bf16 split-GEMM, cp.async pipeline, pre-split operands.
//   CTA: D[128 m, 64 j]; K=1024 in 64-chunks. grid (16 j-tiles, 8 m-tiles).
//   smem per stage: Ahi(17408) Alo(17408) Bhi(9216) Blo(9216) = 53248; x2.
// ---------------------------------------------------------------------------
#define A_STRIDE_B 272
#define B_STRIDE_B 144
#define ST_AHI 0
#define ST_ALO 17408
#define ST_BHI 34816
#define ST_BLO 44032
#define STAGE_STRIDE 53248
#define GEMM_SMEM (2 * STAGE_STRIDE)   // 106496

__global__ void __launch_bounds__(256)
gemm_mma_kernel() {
    extern __shared__ __align__(16) char smp[];
    const uint32_t sb = smem_u32(smp);

    const int tid  = threadIdx.x;
    const int lane = tid & 31;
    const int wid  = tid >> 5;
    const int warp_m = (wid & 3) * 32;
    const int warp_j = (wid >> 2) * 32;
    const int mcta = blockIdx.y * 128;
    const int bx   = blockIdx.x;
    const int j0   = bx * 64;

    // ldmatrix per-lane addresses (validated in R5)
    const int aK = (lane & 7) + ((lane & 16) ? 8 : 0);
    const int aM = (lane & 8) ? 8 : 0;
    const int bK = (lane & 7) + ((lane & 8) ? 8 : 0);
    const int bJ = (lane & 16) ? 8 : 0;
    const uint32_t aBase = sb + ST_AHI + (uint32_t)(aK * A_STRIDE_B + (warp_m + aM) * 2);
    const uint32_t bBase = sb + ST_BHI + (uint32_t)(bK * B_STRIDE_B + (warp_j + bJ) * 2);

    float acc[2][4][4];
    #pragma unroll
    for (int mt = 0; mt < 2; mt++)
        #pragma unroll
        for (int nt = 0; nt < 4; nt++)
            #pragma unroll
            for (int r = 0; r < 4; r++) acc[mt][nt][r] = 0.f;

    auto issue_chunk = [&](int it) {
        const int s = it & 1;
        const int k0 = it * 64;
        const uint32_t stg = sb + s * STAGE_STRIDE;
        // A tiles: 64 rows x 256B data, hi+lo
        #pragma unroll
        for (int i = 0; i < 4; i++) {
            int c = tid + i * 256;
            int row = c >> 4, col = c & 15;
            uint32_t dst = stg + row * A_STRIDE_B + col * 16;
            const char* sh = (const char*)g_Ahi + (size_t)(k0 + row) * 2048 + mcta * 2 + col * 16;
            const char* sl = (const char*)g_Alo + (size_t)(k0 + row) * 2048 + mcta * 2 + col * 16;
            cp16(dst + ST_AHI, sh);
            cp16(dst + ST_ALO, sl);
        }
        // B tiles: 64 rows x 128B data, hi+lo
        #pragma unroll
        for (int i = 0; i < 2; i++) {
            int c = tid + i * 256;
            int row = c >> 3, col = c & 7;
            uint32_t dst = stg + row * B_STRIDE_B + col * 16;
            const char* sh = (const char*)g_Bhi + (size_t)(k0 + row) * 2048 + j0 * 2 + col * 16;
            const char* sl = (const char*)g_Blo + (size_t)(k0 + row) * 2048 + j0 * 2 + col * 16;
            cp16(dst + ST_BHI, sh);
            cp16(dst + ST_BLO, sl);
        }
        asm volatile("cp.async.commit_group;" ::: "memory");
    };

    auto compute = [&](int s) {
        const uint32_t aS = aBase + s * STAGE_STRIDE;
        const uint32_t bS = bBase + s * STAGE_STRIDE;
        #pragma unroll
        for (int ks = 0; ks < 4; ks++) {
            uint32_t aKaddr = aS + ks * (16 * A_STRIDE_B);
            uint32_t bKaddr = bS + ks * (16 * B_STRIDE_B);
            uint32_t ah[2][4], al[2][4], bh[2][4], bl[2][4];
            ldsm_x4_t(ah[0][0], ah[0][1], ah[0][2], ah[0][3], aKaddr);
            ldsm_x4_t(ah[1][0], ah[1][1], ah[1][2], ah[1][3], aKaddr + 32);
            ldsm_x4_t(al[0][0], al[0][1], al[0][2], al[0][3], aKaddr + (ST_ALO - ST_AHI));
            ldsm_x4_t(al[1][0], al[1][1], al[1][2], al[1][3], aKaddr + (ST_ALO - ST_AHI) + 32);
            ldsm_x4_t(bh[0][0], bh[0][1], bh[0][2], bh[0][3], bKaddr);
            ldsm_x4_t(bh[1][0], bh[1][1], bh[1][2], bh[1][3], bKaddr + 32);
            ldsm_x4_t(bl[0][0], bl[0][1], bl[0][2], bl[0][3], bKaddr + (ST_BLO - ST_BHI));
            ldsm_x4_t(bl[1][0], bl[1][1], bl[1][2], bl[1][3], bKaddr + (ST_BLO - ST_BHI) + 32);
            #pragma unroll
            for (int mt = 0; mt < 2; mt++)
                #pragma unroll
                for (int nt = 0; nt < 4; nt++) {
                    const uint32_t* Bh = &bh[nt >> 1][(nt & 1) * 2];
                    const uint32_t* Bl = &bl[nt >> 1][(nt & 1) * 2];
                    mma16816(acc[mt][nt], ah[mt], Bh);
                    mma16816(acc[mt][nt], ah[mt], Bl);
                    mma16816(acc[mt][nt], al[mt], Bh);
                }
        }
    };

    issue_chunk(0);
    issue_chunk(1);
    for (int it = 0; it < 16; ++it) {
        if (it < 15) asm volatile("cp.async.wait_group 1;" ::: "memory");
        else         asm volatile("cp.async.wait_group 0;" ::: "memory");
        __syncthreads();
        compute(it & 1);
        __syncthreads();
        if (it < 14) issue_chunk(it + 2);
    }

    // epilogue: acc -> g_S
    const int gid = lane >> 2, tig = lane & 3;
    const int jw = j0 + warp_j + 2 * tig;
    #pragma unroll
    for (int mt = 0; mt < 2; mt++) {
        int m = mcta + warp_m + mt * 16 + gid;
        #pragma unroll
        for (int nt = 0; nt < 4; nt++) {
            int j = jw + nt * 8;
            *(float2*)&g_S[m * 1024 + j] =
                make_float2(acc[mt][nt][0], acc[mt][nt][1]);
            *(float2*)&g_S[(m + 8) * 1024 + j] =
                make_float2(acc[mt][nt][2], acc[mt][nt][3]);
        }
    }
}

// ---------------------------------------------------------------------------
// Kernel 4: per-element tail, packed f32x2, E=4. 512 blocks x 256.
// ---------------------------------------------------------------------------
__global__ void __launch_bounds__(256)
final_kernel(const float* __restrict__ x,
             const int*   __restrict__ mask,
             const float* __restrict__ b_fs,
             float* __restrict__ out) {
    __shared__ u64t pc0[64], pc1[64], pc2[64], pc3[64], pc4[64], pc5[64], pbt[64];
    __shared__ float skn[127], ssl[65], sit[65];
    __shared__ u64t pg[6];
    int t = threadIdx.x;
    if (t < 64) {
        float c;
        c = g_C[t];       pc0[t] = pack2(c, c);
        c = g_C[64 + t];  pc1[t] = pack2(c, c);
        c = g_C[128 + t]; pc2[t] = pack2(c, c);
        c = g_C[192 + t]; pc3[t] = pack2(c, c);
        c = g_C[256 + t]; pc4[t] = pack2(c, c);
        c = g_C[320 + t]; pc5[t] = pack2(c, c);
        c = g_beta[t];    pbt[t] = pack2(c, c);
    }
    if (t < 127) skn[t] = g_knots[t];
    if (t < 65) { ssl[t] = g_slope[t]; sit[t] = g_inter[t]; }
    if (t < 6) { float g = g_gamma[t]; pg[t] = pack2(g, g); }
    __syncthreads();

    const float bfs0 = b_fs[0];
    const int base = blockIdx.x * 1024 + t;

    float x1[4], mf[4], s1[4], s2[4], csv[4];
    #pragma unroll
    for (int e = 0; e < 4; e++) {
        int idx = base + e * 256;
        int mi = mask[idx];
        float xv = x[idx];
        mf[e] = (float)mi;
        x1[e] = mi ? xv : bfs0;
        int n = (idx >> 6) & (Ndim - 1);
        int b = idx >> 16;
        int tt = idx & 63;
        int j = (b << 6) | tt;
        s1[e] = g_S[n * 1024 + j];
        s2[e] = g_S[n * 1024 + 512 + j];
        csv[e] = g_cs[n];
    }

    u64t X1a = pack2(x1[0], x1[1]), X1b = pack2(x1[2], x1[3]);
    u64t MFa = pack2(mf[0], mf[1]), MFb = pack2(mf[2], mf[3]);
    u64t S1a = pack2(s1[0], s1[1]), S1b = pack2(s1[2], s1[3]);
    u64t S2a = pack2(s2[0], s2[1]), S2b = pack2(s2[2], s2[3]);
    u64t CSa = pack2(csv[0], csv[1]), CSb = pack2(csv[2], csv[3]);
    u64t ACCa = 0ull, ACCb = 0ull;

    #pragma unroll
    for (int o = 0; o < 64; o++) {
        u64t K0 = pc0[o], K1 = pc1[o], K2 = pc2[o], K3 = pc3[o];
        u64t K4 = pc4[o], K5 = pc5[o], BT = pbt[o];
        u64t va = fma2(K4, CSa, K5);
        va = fma2(K1, MFa, va);
        va = fma2(K3, S2a, va);
        va = fma2(K2, S1a, va);
        va = fma2(K0, X1a, va);
        ACCa = fma2(BT, abs2(va), ACCa);
        u64t vb = fma2(K4, CSb, K5);
        vb = fma2(K1, MFb, vb);
        vb = fma2(K3, S2b, vb);
        vb = fma2(K2, S1b, vb);
        vb = fma2(K0, X1b, vb);
        ACCb = fma2(BT, abs2(vb), ACCb);
    }

    u64t xsA = fma2(pg[0], X1a, pg[5]);
    xsA = fma2(pg[1], MFa, xsA);
    xsA = fma2(pg[2], S1a, xsA);
    xsA = fma2(pg[3], S2a, xsA);
    xsA = fma2(pg[4], CSa, xsA);
    xsA = add2(xsA, ACCa);
    u64t xsB = fma2(pg[0], X1b, pg[5]);
    xsB = fma2(pg[1], MFb, xsB);
    xsB = fma2(pg[2], S1b, xsB);
    xsB = fma2(pg[3], S2b, xsB);
    xsB = fma2(pg[4], CSb, xsB);
    xsB = add2(xsB, ACCb);

    float xs[4];
    unpack2(xs[0], xs[1], xsA);
    unpack2(xs[2], xs[3], xsB);

    #pragma unroll
    for (int e = 0; e < 4; e++) {
        float v = xs[e];
        int k = 0;
        if (skn[63] < v) k = 64;
        if (skn[k + 31] < v) k += 32;
        if (skn[k + 15] < v) k += 16;
        if (skn[k + 7] < v) k += 8;
        if (skn[k + 3] < v) k += 4;
        if (skn[k + 1] < v) k += 2;
        if (skn[k] < v) k += 1;
        out[base + e * 256] = fmaf(ssl[k], v, sit[k]);
    }
}

// ---------------------------------------------------------------------------
extern "C" void kernel_launch(void* const* d_in, const int* in_sizes, int n_in,
                              void* d_out, int out_size) {
    const float* x     = (const float*)d_in[0];
    const int*   mask  = (const int*)  d_in[1];
    const float* b_fs  = (const float*)d_in[3];
    const float* W_in  = (const float*)d_in[4];
    const float* b_in  = (const float*)d_in[5];
    const float* adj   = (const float*)d_in[6];
    const float* W_gc  = (const float*)d_in[7];
    const float* b_gc  = (const float*)d_in[8];
    const float* W_lo  = (const float*)d_in[9];
    const float* b_lo  = (const float*)d_in[10];
    const float* pre_a = (const float*)d_in[11];
    const float* W_ro  = (const float*)d_in[12];
    const float* b_ro  = (const float*)d_in[13];
    const float* W_o1  = (const float*)d_in[14];
    const float* b_o1  = (const float*)d_in[15];
    const float* W_o2  = (const float*)d_in[16];
    const float* b_o2  = (const float*)d_in[17];
    float* out = (float*)d_out;

    cudaFuncSetAttribute(gemm_mma_kernel,
                         cudaFuncAttributeMaxDynamicSharedMemorySize,
                         GEMM_SMEM);

    prep_kernel<<<1024, 256>>>(adj, x, mask, b_fs);
    coeff_kernel<<<1, 128>>>(W_in, b_in, W_gc, b_gc, W_lo, b_lo,
                             pre_a, W_ro, b_ro, W_o1, b_o1, W_o2, b_o2);
    colsum_kernel<<<128, 256>>>(adj);
    {
        dim3 grid(16, 8);
        gemm_mma_kernel<<<grid, 256, GEMM_SMEM>>>();
    }
    final_kernel<<<512, 256>>>(x, mask, b_fs, out);
}